// round 8
// baseline (speedup 1.0000x reference)
#include <cuda_runtime.h>
#include <cstdint>
#include <mma.h>

using namespace nvcuda;

#define H  128
#define NH 8
#define NQ 2304

__device__ float g_WT[12 * H * H];
__device__ float g_u [NQ * 1024];
__device__ float g_w [NQ * 1024];
__device__ float g_vb[NQ * 1024];
__device__ float g_rb[NQ * 1024];
__device__ float g_buf0[NQ * H];
__device__ float g_buf1[NQ * H];

__global__ void transpose_k(const float* p0, const float* p1, const float* p2,
                            const float* p3, const float* p4, const float* p5)
{
    const float* ps[6] = {p0, p1, p2, p3, p4, p5};
    int slot = blockIdx.x >> 2;                  // 0..11
    int part = blockIdx.x & 3;
    const float* Wm = ps[slot >> 1] + (slot & 1) * H * H;
    float* O = g_WT + slot * H * H;
    int t = threadIdx.x;
    for (int c = part * 32; c < part * 32 + 32; ++c)
        O[c * H + t] = Wm[t * H + c];
}

__device__ __forceinline__ void cp16(uint32_t dst, const float* src) {
    asm volatile("cp.async.cg.shared.global [%0], [%1], 16;" :: "r"(dst), "l"(src));
}

// ====================== tf32 split-3 wmma machinery ==========================
typedef wmma::fragment<wmma::matrix_a, 16, 16, 8, wmma::precision::tf32, wmma::row_major> FragA;
typedef wmma::fragment<wmma::matrix_b, 16, 16, 8, wmma::precision::tf32, wmma::row_major> FragB;
typedef wmma::fragment<wmma::accumulator, 16, 16, 8, float> FragC;

__device__ __forceinline__ float to_tf32_rn(float x) {
    float r;
    asm("cvt.rna.tf32.f32 %0, %1;" : "=f"(r) : "f"(x));
    return r;
}

__device__ __forceinline__ void load_split_a(FragA& hi, FragA& lo, const float* p, unsigned ld) {
    FragA f;
    wmma::load_matrix_sync(f, p, ld);
    #pragma unroll
    for (int i = 0; i < f.num_elements; ++i) {
        float v = f.x[i];
        float h = to_tf32_rn(v);
        hi.x[i] = h;
        lo.x[i] = to_tf32_rn(v - h);
    }
}
__device__ __forceinline__ void load_split_b(FragB& hi, FragB& lo, const float* p, unsigned ld) {
    FragB f;
    wmma::load_matrix_sync(f, p, ld);
    #pragma unroll
    for (int i = 0; i < f.num_elements; ++i) {
        float v = f.x[i];
        float h = to_tf32_rn(v);
        hi.x[i] = h;
        lo.x[i] = to_tf32_rn(v - h);
    }
}
__device__ __forceinline__ void mma3(FragC& c, const FragA& ah, const FragA& al,
                                     const FragB& bh, const FragB& bl) {
    wmma::mma_sync(c, ah, bh, c);
    wmma::mma_sync(c, ah, bl, c);
    wmma::mma_sync(c, al, bh, c);
}

// ---------------- Kernel B: weight-free attention core (unchanged) -----------
__global__ __launch_bounds__(128) void attn_core(
    const float* __restrict__ gu, const float* __restrict__ gw,
    const float* __restrict__ ksrc, const float* __restrict__ rpesrc,
    const int* __restrict__ knn, const unsigned char* __restrict__ mask,
    float* __restrict__ gvb, float* __restrict__ grb,
    int stage, int S)
{
    extern __shared__ float sm[];
    float* sm_u   = sm;              // 1024
    float* sm_w   = sm + 1024;       // 1024
    float* sm_sc  = sm + 2048;       // 512
    float* sm_sc1 = sm + 2560;       // 512
    float* sm_k   = sm + 3072;       // S*132
    float* sm_r   = sm_k + S * 132;  // S*132

    __shared__ int kbase[64], rbase[64], mflag[64];

    const int q = blockIdx.x;
    const int t = threadIdx.x;

    if (t < S) {
        int kb, rb, mf;
        if (stage == 1) {
            kb = (q * S + t) * H; rb = kb;
            mf = mask[q * S + t];
        } else if (stage == 2) {
            int idx = knn[q * 32 + t];
            kb = (q * 128 + idx) * H; rb = kb;
            mf = mask[q * 128 + idx];
        } else {
            int g = q / 48, qn = q % 48;
            int idx = knn[(g * 48 + qn) * 16 + t];
            kb = ((g * 48 + idx) * 50 + 49) * H;
            rb = ((g * 48 + qn) * 48 + idx) * H;
            mf = mask[(g * 48 + qn) * 48 + idx];
        }
        kbase[t] = kb; rbase[t] = rb; mflag[t] = mf;
    }
    __syncthreads();

    {
        uint32_t su  = (uint32_t)__cvta_generic_to_shared(sm_u);
        uint32_t sw  = (uint32_t)__cvta_generic_to_shared(sm_w);
        for (int c = t; c < 256; c += 128) {
            cp16(su + c * 16, gu + q * 1024 + c * 4);
            cp16(sw + c * 16, gw + q * 1024 + c * 4);
        }
        uint32_t smk = (uint32_t)__cvta_generic_to_shared(sm_k);
        uint32_t smr = (uint32_t)__cvta_generic_to_shared(sm_r);
        for (int c = t; c < S * 32; c += 128) {
            int s = c >> 5, j = c & 31;
            cp16(smk + s * 528 + j * 16, ksrc   + kbase[s] + j * 4);
            cp16(smr + s * 528 + j * 16, rpesrc + rbase[s] + j * 4);
        }
        asm volatile("cp.async.commit_group;");
        asm volatile("cp.async.wait_group 0;");
    }
    __syncthreads();

    {
        int half = t >> 6, s = t & 63;
        if (s < S) {
            const float* kk = &sm_k[s * 132 + half * 64];
            const float* rr = &sm_r[s * 132 + half * 64];
            float acc[NH];
            #pragma unroll
            for (int n = 0; n < NH; ++n) acc[n] = 0.f;
            #pragma unroll 4
            for (int i = 0; i < 64; i += 4) {
                float4 k4 = *(const float4*)(kk + i);
                float4 r4 = *(const float4*)(rr + i);
                #pragma unroll
                for (int n = 0; n < NH; ++n) {
                    float4 u4 = *(const float4*)(sm_u + n * H + half * 64 + i);
                    float4 w4 = *(const float4*)(sm_w + n * H + half * 64 + i);
                    acc[n] += k4.x * u4.x + k4.y * u4.y + k4.z * u4.z + k4.w * u4.w
                            + r4.x * w4.x + r4.y * w4.y + r4.z * w4.z + r4.w * w4.w;
                }
            }
            float* dst = half ? sm_sc1 : sm_sc;
            #pragma unroll
            for (int n = 0; n < NH; ++n) dst[s * NH + n] = acc[n];
        }
    }
    __syncthreads();

    if (t < 64) {
        int n = t >> 3, j = t & 7;
        float mx = -1e30f;
        for (int s = j; s < S; s += 8) {
            float v = (sm_sc[s * NH + n] + sm_sc1[s * NH + n]) * 0.25f;
            if (mflag[s]) v = -1e9f;
            sm_sc[s * NH + n] = v;
            mx = fmaxf(mx, v);
        }
        #pragma unroll
        for (int o = 4; o; o >>= 1) mx = fmaxf(mx, __shfl_xor_sync(0xffffffffu, mx, o));
        float sum = 0.f;
        for (int s = j; s < S; s += 8) {
            float p = __expf(sm_sc[s * NH + n] - mx);
            sm_sc[s * NH + n] = p; sum += p;
        }
        #pragma unroll
        for (int o = 4; o; o >>= 1) sum += __shfl_xor_sync(0xffffffffu, sum, o);
        float inv = 1.f / sum;
        for (int s = j; s < S; s += 8) sm_sc[s * NH + n] *= inv;
    }
    __syncthreads();

    {
        float vb[NH], rb2[NH];
        #pragma unroll
        for (int n = 0; n < NH; ++n) { vb[n] = 0.f; rb2[n] = 0.f; }
        for (int s = 0; s < S; ++s) {
            float kv = sm_k[s * 132 + t];
            float rv = sm_r[s * 132 + t];
            float4 p0 = *(const float4*)&sm_sc[s * NH];
            float4 p1 = *(const float4*)&sm_sc[s * NH + 4];
            vb[0] += p0.x * kv;  rb2[0] += p0.x * rv;
            vb[1] += p0.y * kv;  rb2[1] += p0.y * rv;
            vb[2] += p0.z * kv;  rb2[2] += p0.z * rv;
            vb[3] += p0.w * kv;  rb2[3] += p0.w * rv;
            vb[4] += p1.x * kv;  rb2[4] += p1.x * rv;
            vb[5] += p1.y * kv;  rb2[5] += p1.y * rv;
            vb[6] += p1.z * kv;  rb2[6] += p1.z * rv;
            vb[7] += p1.w * kv;  rb2[7] += p1.w * rv;
        }
        #pragma unroll
        for (int n = 0; n < NH; ++n) {
            gvb[q * 1024 + n * H + t] = vb[n];
            grb[q * 1024 + n * H + t] = rb2[n];
        }
    }
}

// ---------------- tail_fused: of/Wo/+x then next-stage qh & u/w (wmma) -------
// block = 16 queries, 256 threads (8 warps). grid = 144.
__global__ __launch_bounds__(256) void tail_fused(
    const float* __restrict__ xin,
    const float* __restrict__ gvb, const float* __restrict__ grb,
    const float* __restrict__ Wv, const float* __restrict__ Wrv,
    const float* __restrict__ Wo,
    float* __restrict__ xout,
    const float* __restrict__ Wq2,
    const float* __restrict__ WkT2, const float* __restrict__ WrkT2,
    float* __restrict__ gu, float* __restrict__ gw,
    int do_of, int do_next)
{
    __shared__ __align__(16) float s_of[16 * 136];
    __shared__ __align__(16) float s_x [16 * 136];
    __shared__ __align__(16) float s_qh[16 * 136];

    const int tid = threadIdx.x;
    const int w   = tid >> 5;            // warp 0..7
    const int q0  = blockIdx.x * 16;

    FragA ah, al;
    FragB bh, bl;
    FragC acc;

    if (do_of) {
        // ---- of[:, 16w..16w+16] = vb_w @ Wv_cols + rb_w @ Wrv_cols (warp = head w)
        wmma::fill_fragment(acc, 0.f);
        #pragma unroll 1
        for (int kk = 0; kk < 16; ++kk) {
            load_split_a(ah, al, gvb + q0 * 1024 + w * 128 + kk * 8, 1024);
            load_split_b(bh, bl, Wv + kk * 8 * H + 16 * w, H);
            mma3(acc, ah, al, bh, bl);
        }
        #pragma unroll 1
        for (int kk = 0; kk < 16; ++kk) {
            load_split_a(ah, al, grb + q0 * 1024 + w * 128 + kk * 8, 1024);
            load_split_b(bh, bl, Wrv + kk * 8 * H + 16 * w, H);
            mma3(acc, ah, al, bh, bl);
        }
        wmma::store_matrix_sync(s_of + 16 * w, acc, 136, wmma::mem_row_major);
        __syncthreads();

        // ---- xdelta[:, 16w..] = of @ Wo
        wmma::fill_fragment(acc, 0.f);
        #pragma unroll 1
        for (int kk = 0; kk < 16; ++kk) {
            load_split_a(ah, al, s_of + kk * 8, 136);
            load_split_b(bh, bl, Wo + kk * 8 * H + 16 * w, H);
            mma3(acc, ah, al, bh, bl);
        }
        wmma::store_matrix_sync(s_x + 16 * w, acc, 136, wmma::mem_row_major);
        __syncthreads();

        // ---- x_out = x + delta; write gmem + keep in smem
        for (int e = tid; e < 16 * 128; e += 256) {
            int r = e >> 7, c = e & 127;
            float v = s_x[r * 136 + c] + xin[(q0 + r) * H + c];
            s_x[r * 136 + c] = v;
            xout[(q0 + r) * H + c] = v;
        }
        __syncthreads();
    } else {
        // first stage: just stage x into smem
        for (int e = tid; e < 16 * 128; e += 256) {
            int r = e >> 7, c = e & 127;
            s_x[r * 136 + c] = xin[(q0 + r) * H + c];
        }
        __syncthreads();
    }

    if (!do_next) return;

    // ---- qh[:, 16w..] = x @ Wq2
    wmma::fill_fragment(acc, 0.f);
    #pragma unroll 1
    for (int kk = 0; kk < 16; ++kk) {
        load_split_a(ah, al, s_x + kk * 8, 136);
        load_split_b(bh, bl, Wq2 + kk * 8 * H + 16 * w, H);
        mma3(acc, ah, al, bh, bl);
    }
    wmma::store_matrix_sync(s_qh + 16 * w, acc, 136, wmma::mem_row_major);
    __syncthreads();

    // ---- u/w for head w:  u[:, w*128+16j..] = qh[:, 16w..16w+16] @ WkT2[16w.., :]
    FragA ah0, al0, ah1, al1;
    load_split_a(ah0, al0, s_qh + 16 * w,     136);
    load_split_a(ah1, al1, s_qh + 16 * w + 8, 136);
    #pragma unroll 1
    for (int j = 0; j < 8; ++j) {
        wmma::fill_fragment(acc, 0.f);
        load_split_b(bh, bl, WkT2 + (16 * w    ) * H + 16 * j, H);
        mma3(acc, ah0, al0, bh, bl);
        load_split_b(bh, bl, WkT2 + (16 * w + 8) * H + 16 * j, H);
        mma3(acc, ah1, al1, bh, bl);
        wmma::store_matrix_sync(gu + q0 * 1024 + w * 128 + 16 * j, acc, 1024,
                                wmma::mem_row_major);

        wmma::fill_fragment(acc, 0.f);
        load_split_b(bh, bl, WrkT2 + (16 * w    ) * H + 16 * j, H);
        mma3(acc, ah0, al0, bh, bl);
        load_split_b(bh, bl, WrkT2 + (16 * w + 8) * H + 16 * j, H);
        mma3(acc, ah1, al1, bh, bl);
        wmma::store_matrix_sync(gw + q0 * 1024 + w * 128 + 16 * j, acc, 1024,
                                wmma::mem_row_major);
    }
}

extern "C" void kernel_launch(void* const* d_in, const int* in_sizes, int n_in,
                              void* d_out, int out_size)
{
    bool sig = (in_sizes[6] == 32768);

    const float* x_m    = (const float*)d_in[0];
    const float* x_a    = (const float*)d_in[1];
    const float* x_pl   = (const float*)d_in[2];
    const float* rpe_t  = (const float*)d_in[3];
    const float* rpe_pl = (const float*)d_in[4];
    const float* rpe_a  = (const float*)d_in[5];

    const float* W[3][6];
    int wb = sig ? 6 : 11;
    for (int s = 0; s < 3; ++s)
        for (int j = 0; j < 6; ++j)
            W[s][j] = (const float*)d_in[wb + s * 6 + j];

    int kb = sig ? 24 : 6;
    const int* knn_pl = (const int*)d_in[kb + 0];
    const int* knn_a  = (const int*)d_in[kb + 1];
    const unsigned char* mk_t  = (const unsigned char*)d_in[kb + 2];
    const unsigned char* mk_pl = (const unsigned char*)d_in[kb + 3];
    const unsigned char* mk_a  = (const unsigned char*)d_in[kb + 4];

    cudaFuncSetAttribute(attn_core, cudaFuncAttributeMaxDynamicSharedMemorySize, 65088);

    float *buf0, *buf1, *wt, *gu, *gw, *gvb, *grb;
    cudaGetSymbolAddress((void**)&buf0, g_buf0);
    cudaGetSymbolAddress((void**)&buf1, g_buf1);
    cudaGetSymbolAddress((void**)&wt,   g_WT);
    cudaGetSymbolAddress((void**)&gu,   g_u);
    cudaGetSymbolAddress((void**)&gw,   g_w);
    cudaGetSymbolAddress((void**)&gvb,  g_vb);
    cudaGetSymbolAddress((void**)&grb,  g_rb);

    transpose_k<<<48, 128>>>(W[0][1], W[0][3], W[1][1], W[1][3], W[2][1], W[2][3]);

    const int Ss[3] = {50, 32, 16};
    const float* cur = x_m;
    float* bufs[2] = {buf0, buf1};
    int bi = 0;

    // First-stage u/w (no of phase).
    tail_fused<<<NQ / 16, 256>>>(x_m, gvb, grb,
                                 W[0][2], W[0][4], W[0][5],   // unused (do_of=0)
                                 buf0,                         // unused
                                 W[0][0],
                                 wt + ((0 * 2 + 0) * 2 + 0) * H * H,
                                 wt + ((0 * 2 + 1) * 2 + 0) * H * H,
                                 gu, gw, /*do_of=*/0, /*do_next=*/1);

    for (int idx = 0; idx < 6; ++idx) {
        int l = idx / 3, s = idx % 3;
        int l2 = (idx + 1) / 3, s2 = (idx + 1) % 3;
        float* outp = (idx == 5) ? (float*)d_out : bufs[bi];
        int S = Ss[s];
        const float* ksrc = (s == 1) ? x_pl : x_a;
        const float* rp   = (s == 0) ? rpe_t : (s == 1) ? rpe_pl : rpe_a;
        const int*   kn   = (s == 1) ? knn_pl : (s == 2) ? knn_a : (const int*)0;
        const unsigned char* mk = (s == 0) ? mk_t : (s == 1) ? mk_pl : mk_a;

        const float* Wv  = W[s][2] + l * H * H;
        const float* Wrv = W[s][4] + l * H * H;
        const float* Wo  = W[s][5] + l * H * H;

        size_t smemB = (size_t)(3072 + S * 264) * sizeof(float);
        attn_core<<<NQ, 128, smemB>>>(gu, gw, ksrc, rp, kn, mk,
                                      gvb, grb, s + 1, S);

        int do_next = (idx < 5);
        const float* Wq2   = do_next ? W[s2][0] + l2 * H * H : W[0][0];
        const float* WkT2  = do_next ? wt + ((s2 * 2 + 0) * 2 + l2) * H * H : wt;
        const float* WrkT2 = do_next ? wt + ((s2 * 2 + 1) * 2 + l2) * H * H : wt;

        tail_fused<<<NQ / 16, 256>>>(cur, gvb, grb, Wv, Wrv, Wo, outp,
                                     Wq2, WkT2, WrkT2, gu, gw,
                                     /*do_of=*/1, do_next);
        cur = outp;
        bi ^= 1;
    }
}

// round 9
// speedup vs baseline: 1.4212x; 1.4212x over previous
#include <cuda_runtime.h>
#include <cstdint>

#define H  128
#define NH 8
#define NQ 2304

__device__ float g_WT[12 * H * H];
__device__ float g_u [NQ * 1024];
__device__ float g_w [NQ * 1024];
__device__ float g_vb[NQ * 1024];   // layout: [q>>2][n*128+i][q&3]
__device__ float g_rb[NQ * 1024];   // same
__device__ float g_buf0[NQ * H];
__device__ float g_buf1[NQ * H];

__global__ void transpose_k(const float* p0, const float* p1, const float* p2,
                            const float* p3, const float* p4, const float* p5)
{
    const float* ps[6] = {p0, p1, p2, p3, p4, p5};
    int slot = blockIdx.x >> 2;                  // 0..11
    int part = blockIdx.x & 3;
    const float* Wm = ps[slot >> 1] + (slot & 1) * H * H;
    float* O = g_WT + slot * H * H;
    int t = threadIdx.x;
    for (int c = part * 32; c < part * 32 + 32; ++c)
        O[c * H + t] = Wm[t * H + c];
}

__device__ __forceinline__ void cp16(uint32_t dst, const float* src) {
    asm volatile("cp.async.cg.shared.global [%0], [%1], 16;" :: "r"(dst), "l"(src));
}

// ---- helper: u/w head projection from qh in smem -----------------------------
__device__ __forceinline__ void uw_heads(
    const float (*sqh)[128], int g, int t, int q0,
    const float* __restrict__ WkT, const float* __restrict__ WrkT,
    float* __restrict__ gu, float* __restrict__ gw)
{
    #pragma unroll 1
    for (int nn = 0; nn < 4; ++nn) {
        int n = 4 * g + nn;
        float wk[16], wr[16];
        #pragma unroll
        for (int d = 0; d < 16; ++d) {
            wk[d] = WkT [(n * 16 + d) * H + t];
            wr[d] = WrkT[(n * 16 + d) * H + t];
        }
        float uo[4], wo4[4];
        #pragma unroll
        for (int q = 0; q < 4; ++q) { uo[q] = 0.f; wo4[q] = 0.f; }
        #pragma unroll
        for (int d = 0; d < 16; ++d) {
            #pragma unroll
            for (int q = 0; q < 4; ++q) {
                float qv = sqh[q][n * 16 + d];
                uo[q]  += qv * wk[d];
                wo4[q] += qv * wr[d];
            }
        }
        #pragma unroll
        for (int q = 0; q < 4; ++q) {
            gu[(q0 + q) * 1024 + n * H + t] = uo[q];
            gw[(q0 + q) * 1024 + n * H + t] = wo4[q];
        }
    }
}

// ---------------- Kernel A (first stage only): qh = x@Wq; u/w ----------------
__global__ __launch_bounds__(256) void stage_uw(
    const float* __restrict__ xin,
    const float* __restrict__ Wq,
    const float* __restrict__ WkT, const float* __restrict__ WrkT,
    float* __restrict__ gu, float* __restrict__ gw)
{
    __shared__ float sx [4][128];
    __shared__ float sqh[4][128];
    const int tid = threadIdx.x;
    const int t = tid & 127, g = tid >> 7;
    const int q0 = blockIdx.x * 4;

    for (int e = tid; e < 512; e += 256)
        sx[e >> 7][e & 127] = xin[q0 * H + e];
    __syncthreads();

    {
        float a0 = 0.f, a1 = 0.f;
        const float* x0 = sx[2 * g];
        const float* x1 = sx[2 * g + 1];
        #pragma unroll 8
        for (int i = 0; i < H; ++i) {
            float wv = Wq[i * H + t];
            a0 += x0[i] * wv; a1 += x1[i] * wv;
        }
        sqh[2 * g    ][t] = a0;
        sqh[2 * g + 1][t] = a1;
    }
    __syncthreads();
    uw_heads(sqh, g, t, q0, WkT, WrkT, gu, gw);
}

// ---------------- Kernel B: weight-free attention core -----------------------
__global__ __launch_bounds__(128) void attn_core(
    const float* __restrict__ gu, const float* __restrict__ gw,
    const float* __restrict__ ksrc, const float* __restrict__ rpesrc,
    const int* __restrict__ knn, const unsigned char* __restrict__ mask,
    float* __restrict__ gvb, float* __restrict__ grb,
    int stage, int S)
{
    extern __shared__ float sm[];
    float* sm_u   = sm;              // 1024
    float* sm_w   = sm + 1024;       // 1024
    float* sm_sc  = sm + 2048;       // 512
    float* sm_sc1 = sm + 2560;       // 512
    float* sm_k   = sm + 3072;       // S*132
    float* sm_r   = sm_k + S * 132;  // S*132

    __shared__ int kbase[64], rbase[64], mflag[64];

    const int q = blockIdx.x;
    const int t = threadIdx.x;

    if (t < S) {
        int kb, rb, mf;
        if (stage == 1) {
            kb = (q * S + t) * H; rb = kb;
            mf = mask[q * S + t];
        } else if (stage == 2) {
            int idx = knn[q * 32 + t];
            kb = (q * 128 + idx) * H; rb = kb;
            mf = mask[q * 128 + idx];
        } else {
            int g = q / 48, qn = q % 48;
            int idx = knn[(g * 48 + qn) * 16 + t];
            kb = ((g * 48 + idx) * 50 + 49) * H;
            rb = ((g * 48 + qn) * 48 + idx) * H;
            mf = mask[(g * 48 + qn) * 48 + idx];
        }
        kbase[t] = kb; rbase[t] = rb; mflag[t] = mf;
    }
    __syncthreads();

    {
        uint32_t su  = (uint32_t)__cvta_generic_to_shared(sm_u);
        uint32_t sw  = (uint32_t)__cvta_generic_to_shared(sm_w);
        for (int c = t; c < 256; c += 128) {
            cp16(su + c * 16, gu + q * 1024 + c * 4);
            cp16(sw + c * 16, gw + q * 1024 + c * 4);
        }
        uint32_t smk = (uint32_t)__cvta_generic_to_shared(sm_k);
        uint32_t smr = (uint32_t)__cvta_generic_to_shared(sm_r);
        for (int c = t; c < S * 32; c += 128) {
            int s = c >> 5, j = c & 31;
            cp16(smk + s * 528 + j * 16, ksrc   + kbase[s] + j * 4);
            cp16(smr + s * 528 + j * 16, rpesrc + rbase[s] + j * 4);
        }
        asm volatile("cp.async.commit_group;");
        asm volatile("cp.async.wait_group 0;");
    }
    __syncthreads();

    {
        int half = t >> 6, s = t & 63;
        if (s < S) {
            const float* kk = &sm_k[s * 132 + half * 64];
            const float* rr = &sm_r[s * 132 + half * 64];
            float acc[NH];
            #pragma unroll
            for (int n = 0; n < NH; ++n) acc[n] = 0.f;
            #pragma unroll 4
            for (int i = 0; i < 64; i += 4) {
                float4 k4 = *(const float4*)(kk + i);
                float4 r4 = *(const float4*)(rr + i);
                #pragma unroll
                for (int n = 0; n < NH; ++n) {
                    float4 u4 = *(const float4*)(sm_u + n * H + half * 64 + i);
                    float4 w4 = *(const float4*)(sm_w + n * H + half * 64 + i);
                    acc[n] += k4.x * u4.x + k4.y * u4.y + k4.z * u4.z + k4.w * u4.w
                            + r4.x * w4.x + r4.y * w4.y + r4.z * w4.z + r4.w * w4.w;
                }
            }
            float* dst = half ? sm_sc1 : sm_sc;
            #pragma unroll
            for (int n = 0; n < NH; ++n) dst[s * NH + n] = acc[n];
        }
    }
    __syncthreads();

    if (t < 64) {
        int n = t >> 3, j = t & 7;
        float mx = -1e30f;
        for (int s = j; s < S; s += 8) {
            float v = (sm_sc[s * NH + n] + sm_sc1[s * NH + n]) * 0.25f;
            if (mflag[s]) v = -1e9f;
            sm_sc[s * NH + n] = v;
            mx = fmaxf(mx, v);
        }
        #pragma unroll
        for (int o = 4; o; o >>= 1) mx = fmaxf(mx, __shfl_xor_sync(0xffffffffu, mx, o));
        float sum = 0.f;
        for (int s = j; s < S; s += 8) {
            float p = __expf(sm_sc[s * NH + n] - mx);
            sm_sc[s * NH + n] = p; sum += p;
        }
        #pragma unroll
        for (int o = 4; o; o >>= 1) sum += __shfl_xor_sync(0xffffffffu, sum, o);
        float inv = 1.f / sum;
        for (int s = j; s < S; s += 8) sm_sc[s * NH + n] *= inv;
    }
    __syncthreads();

    {
        float vb[NH], rb2[NH];
        #pragma unroll
        for (int n = 0; n < NH; ++n) { vb[n] = 0.f; rb2[n] = 0.f; }
        for (int s = 0; s < S; ++s) {
            float kv = sm_k[s * 132 + t];
            float rv = sm_r[s * 132 + t];
            float4 p0 = *(const float4*)&sm_sc[s * NH];
            float4 p1 = *(const float4*)&sm_sc[s * NH + 4];
            vb[0] += p0.x * kv;  rb2[0] += p0.x * rv;
            vb[1] += p0.y * kv;  rb2[1] += p0.y * rv;
            vb[2] += p0.z * kv;  rb2[2] += p0.z * rv;
            vb[3] += p0.w * kv;  rb2[3] += p0.w * rv;
            vb[4] += p1.x * kv;  rb2[4] += p1.x * rv;
            vb[5] += p1.y * kv;  rb2[5] += p1.y * rv;
            vb[6] += p1.z * kv;  rb2[6] += p1.z * rv;
            vb[7] += p1.w * kv;  rb2[7] += p1.w * rv;
        }
        // q-interleaved store: [(q>>2)*4096 + (n*128+t)*4 + (q&3)]
        int base = (q & ~3) * 1024 + (q & 3);
        #pragma unroll
        for (int n = 0; n < NH; ++n) {
            gvb[base + (n * 128 + t) * 4] = vb[n];
            grb[base + (n * 128 + t) * 4] = rb2[n];
        }
    }
}

// ---------------- Kernel C+A': out_proj fused with next-stage uw -------------
// block = 4 queries, 256 threads, grid 576.
__global__ __launch_bounds__(256) void out_proj_uw(
    const float* __restrict__ xin,
    const float* __restrict__ gvb, const float* __restrict__ grb,
    const float* __restrict__ Wv, const float* __restrict__ Wrv,
    const float* __restrict__ Wo,
    float* __restrict__ xout,
    const float* __restrict__ Wq2,
    const float* __restrict__ WkT2, const float* __restrict__ WrkT2,
    float* __restrict__ gu, float* __restrict__ gw, int do_next)
{
    __shared__ __align__(16) float svb4[4096];   // [n*128+i][q]
    __shared__ __align__(16) float srb4[4096];
    __shared__ __align__(16) float sof4[512];    // [i][q]
    __shared__ float sxo[4][128];
    __shared__ float part[2][4][128];

    const int tid = threadIdx.x;
    const int t = tid & 127, g = tid >> 7;
    const int q0 = blockIdx.x * 4;
    const int n = t >> 4;
    const int i0 = g * 64;

    // Stage vb/rb into smem (contiguous: q0*1024 == (q0/4)*4096).
    {
        uint32_t a = (uint32_t)__cvta_generic_to_shared(svb4);
        uint32_t b = (uint32_t)__cvta_generic_to_shared(srb4);
        for (int c = tid; c < 1024; c += 256) {
            cp16(a + c * 16, gvb + q0 * 1024 + c * 4);
            cp16(b + c * 16, grb + q0 * 1024 + c * 4);
        }
        asm volatile("cp.async.commit_group;");
        asm volatile("cp.async.wait_group 0;");
    }
    __syncthreads();

    // Phase 1: of[q][t] = vb[q][n]·Wv[:,t] + rb[q][n]·Wrv[:,t]  (i split by group)
    {
        float a0 = 0.f, a1 = 0.f, a2 = 0.f, a3 = 0.f;
        float b0 = 0.f, b1 = 0.f, b2 = 0.f, b3 = 0.f;
        #pragma unroll 4
        for (int ii = 0; ii < 64; ii += 2) {
            int i = i0 + ii;
            float wv0 = Wv [(i    ) * H + t], wr0 = Wrv[(i    ) * H + t];
            float wv1 = Wv [(i + 1) * H + t], wr1 = Wrv[(i + 1) * H + t];
            float4 v0 = *(const float4*)&svb4[(n * 128 + i    ) * 4];
            float4 r0 = *(const float4*)&srb4[(n * 128 + i    ) * 4];
            float4 v1 = *(const float4*)&svb4[(n * 128 + i + 1) * 4];
            float4 r1 = *(const float4*)&srb4[(n * 128 + i + 1) * 4];
            a0 += v0.x * wv0 + r0.x * wr0;  b0 += v1.x * wv1 + r1.x * wr1;
            a1 += v0.y * wv0 + r0.y * wr0;  b1 += v1.y * wv1 + r1.y * wr1;
            a2 += v0.z * wv0 + r0.z * wr0;  b2 += v1.z * wv1 + r1.z * wr1;
            a3 += v0.w * wv0 + r0.w * wr0;  b3 += v1.w * wv1 + r1.w * wr1;
        }
        part[g][0][t] = a0 + b0; part[g][1][t] = a1 + b1;
        part[g][2][t] = a2 + b2; part[g][3][t] = a3 + b3;
    }
    __syncthreads();
    if (g == 0) {
        float4 o;
        o.x = part[0][0][t] + part[1][0][t];
        o.y = part[0][1][t] + part[1][1][t];
        o.z = part[0][2][t] + part[1][2][t];
        o.w = part[0][3][t] + part[1][3][t];
        *(float4*)&sof4[t * 4] = o;
    }
    __syncthreads();

    // Phase 2: x_out = x + of @ Wo  (i split by group)
    {
        float a0 = 0.f, a1 = 0.f, a2 = 0.f, a3 = 0.f;
        float b0 = 0.f, b1 = 0.f, b2 = 0.f, b3 = 0.f;
        #pragma unroll 4
        for (int ii = 0; ii < 64; ii += 2) {
            int i = i0 + ii;
            float wo0 = Wo[(i    ) * H + t];
            float wo1 = Wo[(i + 1) * H + t];
            float4 f0 = *(const float4*)&sof4[(i    ) * 4];
            float4 f1 = *(const float4*)&sof4[(i + 1) * 4];
            a0 += f0.x * wo0;  b0 += f1.x * wo1;
            a1 += f0.y * wo0;  b1 += f1.y * wo1;
            a2 += f0.z * wo0;  b2 += f1.z * wo1;
            a3 += f0.w * wo0;  b3 += f1.w * wo1;
        }
        part[g][0][t] = a0 + b0; part[g][1][t] = a1 + b1;
        part[g][2][t] = a2 + b2; part[g][3][t] = a3 + b3;
    }
    __syncthreads();
    if (g == 0) {
        #pragma unroll
        for (int q = 0; q < 4; ++q) {
            float v = xin[(q0 + q) * H + t] + part[0][q][t] + part[1][q][t];
            sxo[q][t] = v;
            xout[(q0 + q) * H + t] = v;
        }
    }
    __syncthreads();

    if (!do_next) return;

    // Phase 3: next-stage qh = x_out @ Wq2  (group g does queries 2g, 2g+1)
    {
        float a0 = 0.f, a1 = 0.f;
        const float* x0 = sxo[2 * g];
        const float* x1 = sxo[2 * g + 1];
        #pragma unroll 8
        for (int i = 0; i < H; ++i) {
            float wv = Wq2[i * H + t];
            a0 += x0[i] * wv; a1 += x1[i] * wv;
        }
        part[0][2 * g    ][t] = a0;
        part[0][2 * g + 1][t] = a1;
    }
    __syncthreads();

    // Phase 4: next-stage u/w.
    uw_heads((const float (*)[128])part[0], g, t, q0, WkT2, WrkT2, gu, gw);
}

extern "C" void kernel_launch(void* const* d_in, const int* in_sizes, int n_in,
                              void* d_out, int out_size)
{
    bool sig = (in_sizes[6] == 32768);

    const float* x_m    = (const float*)d_in[0];
    const float* x_a    = (const float*)d_in[1];
    const float* x_pl   = (const float*)d_in[2];
    const float* rpe_t  = (const float*)d_in[3];
    const float* rpe_pl = (const float*)d_in[4];
    const float* rpe_a  = (const float*)d_in[5];

    const float* W[3][6];
    int wb = sig ? 6 : 11;
    for (int s = 0; s < 3; ++s)
        for (int j = 0; j < 6; ++j)
            W[s][j] = (const float*)d_in[wb + s * 6 + j];

    int kb = sig ? 24 : 6;
    const int* knn_pl = (const int*)d_in[kb + 0];
    const int* knn_a  = (const int*)d_in[kb + 1];
    const unsigned char* mk_t  = (const unsigned char*)d_in[kb + 2];
    const unsigned char* mk_pl = (const unsigned char*)d_in[kb + 3];
    const unsigned char* mk_a  = (const unsigned char*)d_in[kb + 4];

    cudaFuncSetAttribute(attn_core, cudaFuncAttributeMaxDynamicSharedMemorySize, 65088);

    float *buf0, *buf1, *wt, *gu, *gw, *gvb, *grb;
    cudaGetSymbolAddress((void**)&buf0, g_buf0);
    cudaGetSymbolAddress((void**)&buf1, g_buf1);
    cudaGetSymbolAddress((void**)&wt,   g_WT);
    cudaGetSymbolAddress((void**)&gu,   g_u);
    cudaGetSymbolAddress((void**)&gw,   g_w);
    cudaGetSymbolAddress((void**)&gvb,  g_vb);
    cudaGetSymbolAddress((void**)&grb,  g_rb);

    transpose_k<<<48, 128>>>(W[0][1], W[0][3], W[1][1], W[1][3], W[2][1], W[2][3]);

    const int Ss[3] = {50, 32, 16};
    const float* cur = x_m;
    float* bufs[2] = {buf0, buf1};
    int bi = 0;

    // First-stage u/w.
    stage_uw<<<NQ / 4, 256>>>(x_m, W[0][0],
                              wt + ((0 * 2 + 0) * 2 + 0) * H * H,
                              wt + ((0 * 2 + 1) * 2 + 0) * H * H, gu, gw);

    for (int idx = 0; idx < 6; ++idx) {
        int l = idx / 3, s = idx % 3;
        int l2 = (idx + 1) / 3, s2 = (idx + 1) % 3;
        float* outp = (idx == 5) ? (float*)d_out : bufs[bi];
        int S = Ss[s];
        const float* ksrc = (s == 1) ? x_pl : x_a;
        const float* rp   = (s == 0) ? rpe_t : (s == 1) ? rpe_pl : rpe_a;
        const int*   kn   = (s == 1) ? knn_pl : (s == 2) ? knn_a : (const int*)0;
        const unsigned char* mk = (s == 0) ? mk_t : (s == 1) ? mk_pl : mk_a;

        const float* Wv  = W[s][2] + l * H * H;
        const float* Wrv = W[s][4] + l * H * H;
        const float* Wo  = W[s][5] + l * H * H;

        size_t smemB = (size_t)(3072 + S * 264) * sizeof(float);
        attn_core<<<NQ, 128, smemB>>>(gu, gw, ksrc, rp, kn, mk,
                                      gvb, grb, s + 1, S);

        int do_next = (idx < 5);
        const float* Wq2   = do_next ? W[s2][0] + l2 * H * H : Wv;
        const float* WkT2  = do_next ? wt + ((s2 * 2 + 0) * 2 + l2) * H * H : Wv;
        const float* WrkT2 = do_next ? wt + ((s2 * 2 + 1) * 2 + l2) * H * H : Wv;

        out_proj_uw<<<NQ / 4, 256>>>(cur, gvb, grb, Wv, Wrv, Wo, outp,
                                     Wq2, WkT2, WrkT2, gu, gw, do_next);
        cur = outp;
        bi ^= 1;
    }
}